// round 16
// baseline (speedup 1.0000x reference)
#include <cuda_runtime.h>
#include <cuda_bf16.h>
#include <cstdint>
#include <cstddef>

#define I_DIM 256
#define J_DIM 64
#define N_DIM 384
#define MQ (I_DIM * N_DIM)   /* 98304 query tokens  */
#define MK (J_DIM * N_DIM)   /* 24576 memory tokens */

// ---------------- scratch (device globals; no allocations allowed) ----------
__device__ __nv_bfloat16 g_qe [(size_t)MQ * 256];   // LN(embed) bf16
__device__ __nv_bfloat16 g_km [(size_t)MK * 256];   // LN(memory) bf16
__device__ __nv_bfloat16 g_qg [(size_t)MQ * 512];   // [q | gate] bf16
__device__ __nv_bfloat16 g_kv [(size_t)MK * 512];   // km @ Wkv bf16
__device__ __nv_bfloat16 g_ab [(size_t)MQ * 256];   // gated attention out bf16
__device__ __nv_bfloat16 g_h1 [(size_t)MQ * 512];   // relu FFN hidden bf16
// transposed bf16 weights: Wt[n][k] = W[k][n]
__device__ __nv_bfloat16 g_Wqg[512 * 256];          // rows 0-255 Wq, 256-511 Wgate
__device__ __nv_bfloat16 g_Wkv[512 * 256];
__device__ __nv_bfloat16 g_Wo [256 * 256];
__device__ __nv_bfloat16 g_W1 [512 * 256];
__device__ __nv_bfloat16 g_W2 [256 * 512];

// ======================= sm_80-baseline PTX helpers =========================
__device__ __forceinline__ uint32_t smem_u32(const void* p) {
    uint32_t a;
    asm("{ .reg .u64 t; cvta.to.shared.u64 t, %1; cvt.u32.u64 %0, t; }"
        : "=r"(a) : "l"(p));
    return a;
}
__device__ __forceinline__ void cp_async16(uint32_t saddr, const void* gaddr) {
    asm volatile("cp.async.cg.shared.global [%0], [%1], 16;"
                 :: "r"(saddr), "l"(gaddr) : "memory");
}
#define CP_COMMIT() asm volatile("cp.async.commit_group;" ::: "memory")
#define CP_WAIT(n)  asm volatile("cp.async.wait_group %0;" :: "n"(n) : "memory")

__device__ __forceinline__ void ldsm_x4(uint32_t& r0, uint32_t& r1,
                                        uint32_t& r2, uint32_t& r3, uint32_t addr) {
    asm volatile("ldmatrix.sync.aligned.m8n8.x4.shared.b16 {%0,%1,%2,%3}, [%4];"
                 : "=r"(r0), "=r"(r1), "=r"(r2), "=r"(r3) : "r"(addr));
}
__device__ __forceinline__ void ldsm_x4_trans(uint32_t& r0, uint32_t& r1,
                                              uint32_t& r2, uint32_t& r3, uint32_t addr) {
    asm volatile("ldmatrix.sync.aligned.m8n8.x4.trans.shared.b16 {%0,%1,%2,%3}, [%4];"
                 : "=r"(r0), "=r"(r1), "=r"(r2), "=r"(r3) : "r"(addr));
}
__device__ __forceinline__ void mma16816(float* d, const uint32_t* a, const uint32_t* b) {
    asm volatile("mma.sync.aligned.m16n8k16.row.col.f32.bf16.bf16.f32 "
                 "{%0,%1,%2,%3}, {%4,%5,%6,%7}, {%8,%9}, {%0,%1,%2,%3};"
                 : "+f"(d[0]), "+f"(d[1]), "+f"(d[2]), "+f"(d[3])
                 : "r"(a[0]), "r"(a[1]), "r"(a[2]), "r"(a[3]),
                   "r"(b[0]), "r"(b[1]));
}

#define ROWB 144
#define STG  (128 * ROWB)

// ======== B-resident GEMM (K=256): B panel lives in smem; CTA loops m =======
#define SMEM_BRES (6 * STG)
template <int EPI, bool OUTBF, int MB>
__device__ __forceinline__ void gemm_bres_body(
    char* dsm, const __nv_bfloat16* __restrict__ A,
    const __nv_bfloat16* __restrict__ Bt, void* __restrict__ Cout,
    int Ntot, const float* __restrict__ bias, int n0, int m0_base)
{
    const uint32_t sB = smem_u32(dsm);
    const uint32_t sA = sB + 4 * STG;
    int tid = threadIdx.x, lane = tid & 31, wid = tid >> 5;
    int wm = wid >> 2, wn = wid & 3;
    int crow = tid >> 3, cch = tid & 7;
    int lrow = lane & 7, grp = lane >> 3;
    uint32_t a_off = (uint32_t)((lrow + (grp & 1) * 8) * ROWB + (grp >> 1) * 16);
    uint32_t b_off = (uint32_t)((lrow + (grp >> 1) * 8) * ROWB + (grp & 1) * 16);

    const __nv_bfloat16* Bg = Bt + (size_t)n0 * 256;
    #pragma unroll
    for (int kc = 0; kc < 4; kc++)
        #pragma unroll
        for (int it = 0; it < 4; it++) {
            int row = crow + it * 32;
            cp_async16(sB + kc * STG + row * ROWB + cch * 16,
                       Bg + (size_t)row * 256 + kc * 64 + cch * 8);
        }
    CP_COMMIT();
    {
        const __nv_bfloat16* Ag = A + (size_t)m0_base * 256;
        #pragma unroll
        for (int it = 0; it < 4; it++) {
            int row = crow + it * 32;
            cp_async16(sA + row * ROWB + cch * 16, Ag + (size_t)row * 256 + cch * 8);
        }
    }
    CP_COMMIT();
    CP_WAIT(0);
    __syncthreads();

    float acc[4][4][4];
    #pragma unroll
    for (int i = 0; i < 4; i++)
        #pragma unroll
        for (int j = 0; j < 4; j++)
            #pragma unroll
            for (int u = 0; u < 4; u++) acc[i][j][u] = 0.f;

    const int TOT = MB * 4;
    #pragma unroll 1
    for (int g = 0; g < TOT; g++) {
        int cur = g & 1;
        if (g + 1 < TOT) {
            int g1 = g + 1;
            int mb1 = g1 >> 2, kc1 = g1 & 3;
            const __nv_bfloat16* Agn =
                A + ((size_t)m0_base + (size_t)mb1 * 192 * 128) * 256 + kc1 * 64;
            #pragma unroll
            for (int it = 0; it < 4; it++) {
                int row = crow + it * 32;
                cp_async16(sA + (g1 & 1) * STG + row * ROWB + cch * 16,
                           Agn + (size_t)row * 256 + cch * 8);
            }
            CP_COMMIT();
            CP_WAIT(1);
        } else {
            CP_WAIT(0);
        }
        __syncthreads();

        int kc = g & 3;
        uint32_t aT = sA + cur * STG + (wm * 64) * ROWB + a_off;
        uint32_t bT = sB + kc * STG + (wn * 32) * ROWB + b_off;
        #pragma unroll
        for (int ks = 0; ks < 4; ks++) {
            uint32_t af[4][4], bf[4][2];
            #pragma unroll
            for (int mi = 0; mi < 4; mi++)
                ldsm_x4(af[mi][0], af[mi][1], af[mi][2], af[mi][3],
                        aT + mi * 16 * ROWB + ks * 32);
            #pragma unroll
            for (int np = 0; np < 2; np++) {
                uint32_t r0, r1, r2, r3;
                ldsm_x4(r0, r1, r2, r3, bT + np * 16 * ROWB + ks * 32);
                bf[np * 2][0] = r0; bf[np * 2][1] = r1;
                bf[np * 2 + 1][0] = r2; bf[np * 2 + 1][1] = r3;
            }
            #pragma unroll
            for (int mi = 0; mi < 4; mi++)
                #pragma unroll
                for (int ni = 0; ni < 4; ni++)
                    mma16816(acc[mi][ni], af[mi], bf[ni]);
        }
        __syncthreads();

        if (kc == 3) {
            size_t m0 = (size_t)m0_base + (size_t)(g >> 2) * 192 * 128;
            int qrow = lane >> 2, qcol = (lane & 3) * 2;
            #pragma unroll
            for (int mi = 0; mi < 4; mi++) {
                #pragma unroll
                for (int half = 0; half < 2; half++) {
                    size_t row = m0 + wm * 64 + mi * 16 + qrow + half * 8;
                    #pragma unroll
                    for (int ni = 0; ni < 4; ni++) {
                        int c = n0 + wn * 32 + ni * 8 + qcol;
                        float r0 = acc[mi][ni][half * 2 + 0];
                        float r1 = acc[mi][ni][half * 2 + 1];
                        if (EPI == 1) {
                            r0 = fmaxf(r0 + bias[c], 0.f);
                            r1 = fmaxf(r1 + bias[c + 1], 0.f);
                        }
                        if (OUTBF) {
                            *(__nv_bfloat162*)((__nv_bfloat16*)Cout + row * Ntot + c)
                                = __floats2bfloat162_rn(r0, r1);
                        } else {
                            *(float2*)((float*)Cout + row * Ntot + c) =
                                make_float2(r0, r1);
                        }
                        acc[mi][ni][half * 2 + 0] = 0.f;
                        acc[mi][ni][half * 2 + 1] = 0.f;
                    }
                }
            }
        }
    }
}

// combined q|gate (z=0, 4 m-blocks) + kv (z=1, 1 m-block) projection
__global__ __launch_bounds__(256) void qgkv_gemm(
    const __nv_bfloat16* __restrict__ qe, const __nv_bfloat16* __restrict__ wqg,
    __nv_bfloat16* __restrict__ qgb,
    const __nv_bfloat16* __restrict__ km, const __nv_bfloat16* __restrict__ wkv,
    __nv_bfloat16* __restrict__ kvb)
{
    extern __shared__ char dsm[];
    if (blockIdx.z == 0) {
        gemm_bres_body<0, true, 4>(dsm, qe, wqg, qgb, 512, nullptr,
                                   blockIdx.x * 128, blockIdx.y * 128);
    } else {
        gemm_bres_body<0, true, 1>(dsm, km, wkv, kvb, 512, nullptr,
                                   blockIdx.x * 128, blockIdx.y * 128);
    }
}

// ============ classic double-buffer GEMM (used for FFN2) ====================
template <int EPI, bool OUTBF>
__global__ __launch_bounds__(256) void mma_gemm(
    const __nv_bfloat16* __restrict__ A, const __nv_bfloat16* __restrict__ Bt,
    void* __restrict__ Cout, int Ntot, int Ktot,
    const float* __restrict__ bias, const float* __restrict__ resid,
    const int* __restrict__ rmask)
{
    extern __shared__ char dsm[];
    const uint32_t sA = smem_u32(dsm);
    const uint32_t sB = sA + 2 * STG;
    int tid = threadIdx.x, lane = tid & 31, wid = tid >> 5;
    int wm = wid >> 2, wn = wid & 3;
    int n0 = blockIdx.x * 128, m0 = blockIdx.y * 128;

    const __nv_bfloat16* Ag = A  + (size_t)m0 * Ktot;
    const __nv_bfloat16* Bg = Bt + (size_t)n0 * Ktot;

    int crow = tid >> 3, cch = tid & 7;
    int lrow = lane & 7, grp = lane >> 3;
    uint32_t a_off = (uint32_t)((lrow + (grp & 1) * 8) * ROWB + (grp >> 1) * 16);
    uint32_t b_off = (uint32_t)((lrow + (grp >> 1) * 8) * ROWB + (grp & 1) * 16);

    float acc[4][4][4];
    #pragma unroll
    for (int i = 0; i < 4; i++)
        #pragma unroll
        for (int j = 0; j < 4; j++)
            #pragma unroll
            for (int u = 0; u < 4; u++) acc[i][j][u] = 0.f;

    const int NC = Ktot >> 6;

    #pragma unroll
    for (int it = 0; it < 4; it++) {
        int row = crow + it * 32;
        cp_async16(sA + row * ROWB + cch * 16, Ag + (size_t)row * Ktot + cch * 8);
        cp_async16(sB + row * ROWB + cch * 16, Bg + (size_t)row * Ktot + cch * 8);
    }
    CP_COMMIT();

    for (int kc = 0; kc < NC; kc++) {
        int cur = kc & 1;
        if (kc + 1 < NC) {
            int nxt = cur ^ 1;
            const __nv_bfloat16* Agn = Ag + (kc + 1) * 64;
            const __nv_bfloat16* Bgn = Bg + (kc + 1) * 64;
            #pragma unroll
            for (int it = 0; it < 4; it++) {
                int row = crow + it * 32;
                cp_async16(sA + nxt * STG + row * ROWB + cch * 16,
                           Agn + (size_t)row * Ktot + cch * 8);
                cp_async16(sB + nxt * STG + row * ROWB + cch * 16,
                           Bgn + (size_t)row * Ktot + cch * 8);
            }
            CP_COMMIT();
            CP_WAIT(1);
        } else {
            CP_WAIT(0);
        }
        __syncthreads();

        uint32_t aT = sA + cur * STG + (wm * 64) * ROWB + a_off;
        uint32_t bT = sB + cur * STG + (wn * 32) * ROWB + b_off;
        #pragma unroll
        for (int ks = 0; ks < 4; ks++) {
            uint32_t af[4][4], bf[4][2];
            #pragma unroll
            for (int mi = 0; mi < 4; mi++)
                ldsm_x4(af[mi][0], af[mi][1], af[mi][2], af[mi][3],
                        aT + mi * 16 * ROWB + ks * 32);
            #pragma unroll
            for (int np = 0; np < 2; np++) {
                uint32_t r0, r1, r2, r3;
                ldsm_x4(r0, r1, r2, r3, bT + np * 16 * ROWB + ks * 32);
                bf[np * 2][0] = r0; bf[np * 2][1] = r1;
                bf[np * 2 + 1][0] = r2; bf[np * 2 + 1][1] = r3;
            }
            #pragma unroll
            for (int mi = 0; mi < 4; mi++)
                #pragma unroll
                for (int ni = 0; ni < 4; ni++)
                    mma16816(acc[mi][ni], af[mi], bf[ni]);
        }
        __syncthreads();
    }

    int qrow = lane >> 2, qcol = (lane & 3) * 2;
    #pragma unroll
    for (int mi = 0; mi < 4; mi++) {
        #pragma unroll
        for (int half = 0; half < 2; half++) {
            size_t row = (size_t)m0 + wm * 64 + mi * 16 + qrow + half * 8;
            float mk = 1.f;
            if (EPI >= 2) mk = (float)rmask[row];
            #pragma unroll
            for (int ni = 0; ni < 4; ni++) {
                int c = n0 + wn * 32 + ni * 8 + qcol;
                float r0 = acc[mi][ni][half * 2 + 0];
                float r1 = acc[mi][ni][half * 2 + 1];
                if (EPI == 1) {
                    r0 = fmaxf(r0 + bias[c], 0.f);
                    r1 = fmaxf(r1 + bias[c + 1], 0.f);
                } else if (EPI == 3) {
                    const float* rp = resid + row * Ntot + c;
                    r0 = rp[0] + (r0 + bias[c]) * mk;
                    r1 = rp[1] + (r1 + bias[c + 1]) * mk;
                }
                if (OUTBF) {
                    *(__nv_bfloat162*)((__nv_bfloat16*)Cout + row * Ntot + c) =
                        __floats2bfloat162_rn(r0, r1);
                } else {
                    *(float2*)((float*)Cout + row * Ntot + c) = make_float2(r0, r1);
                }
            }
        }
    }
}

// ======= fused: Wout-GEMM + residual + FFN-LN + FFN1 (h1) ===================
#define STG_A64 (64 * ROWB)
#define STG_B256 (256 * ROWB)
#define ROWH 528
#define GLF_W   33792                       /* 2 pair-slots of 36864 */
#define GLF_RED 107520
#define SMEM_GLN (GLF_RED + 1024 * 4 + 128 * 4)  /* 112128 */
__global__ __launch_bounds__(256, 2) void gemm_ln_ffn1_kernel(
    const __nv_bfloat16* __restrict__ A, const __nv_bfloat16* __restrict__ Bt,
    const float* __restrict__ embed, const int* __restrict__ rmask,
    const float* __restrict__ gam, const float* __restrict__ bet,
    const __nv_bfloat16* __restrict__ w1, const float* __restrict__ b1,
    float* __restrict__ out, __nv_bfloat16* __restrict__ h1)
{
    extern __shared__ char dsm[];
    const uint32_t sA = smem_u32(dsm);
    const uint32_t sB = sA + 2 * STG_A64;
    const uint32_t sH = sA;                  // hln overlays sA/sB after GEMM1
    const uint32_t sW = sA + GLF_W;
    float* sred = (float*)(dsm + GLF_RED);
    float* smu  = sred + 1024;
    float* srs  = smu + 64;
    int tid = threadIdx.x, lane = tid & 31, wn = tid >> 5;
    int m0 = blockIdx.x * 64;

    const __nv_bfloat16* Ag = A + (size_t)m0 * 256;
    const __nv_bfloat16* Bg = Bt;

    int crow = tid >> 3, cch = tid & 7;
    int lrow = lane & 7, grp = lane >> 3;
    uint32_t a_off = (uint32_t)((lrow + (grp & 1) * 8) * ROWB + (grp >> 1) * 16);
    uint32_t b_off = (uint32_t)((lrow + (grp >> 1) * 8) * ROWB + (grp & 1) * 16);

    float acc[4][4][4];
    #pragma unroll
    for (int i = 0; i < 4; i++)
        #pragma unroll
        for (int j = 0; j < 4; j++)
            #pragma unroll
            for (int u = 0; u < 4; u++) acc[i][j][u] = 0.f;

    #pragma unroll
    for (int it = 0; it < 2; it++) {
        int row = crow + it * 32;
        cp_async16(sA + row * ROWB + cch * 16, Ag + (size_t)row * 256 + cch * 8);
    }
    #pragma unroll
    for (int it = 0; it < 8; it++) {
        int row = crow + it * 32;
        cp_async16(sB + row * ROWB + cch * 16, Bg + (size_t)row * 256 + cch * 8);
    }
    CP_COMMIT();

    for (int kc = 0; kc < 4; kc++) {
        int cur = kc & 1;
        if (kc + 1 < 4) {
            int nxt = cur ^ 1;
            const __nv_bfloat16* Agn = Ag + (kc + 1) * 64;
            const __nv_bfloat16* Bgn = Bg + (kc + 1) * 64;
            #pragma unroll
            for (int it = 0; it < 2; it++) {
                int row = crow + it * 32;
                cp_async16(sA + nxt * STG_A64 + row * ROWB + cch * 16,
                           Agn + (size_t)row * 256 + cch * 8);
            }
            #pragma unroll
            for (int it = 0; it < 8; it++) {
                int row = crow + it * 32;
                cp_async16(sB + nxt * STG_B256 + row * ROWB + cch * 16,
                           Bgn + (size_t)row * 256 + cch * 8);
            }
            CP_COMMIT();
            CP_WAIT(1);
        } else {
            CP_WAIT(0);
        }
        __syncthreads();

        uint32_t aT = sA + cur * STG_A64 + a_off;
        uint32_t bT = sB + cur * STG_B256 + (wn * 32) * ROWB + b_off;
        #pragma unroll
        for (int ks = 0; ks < 4; ks++) {
            uint32_t af[4][4], bf[4][2];
            #pragma unroll
            for (int mi = 0; mi < 4; mi++)
                ldsm_x4(af[mi][0], af[mi][1], af[mi][2], af[mi][3],
                        aT + mi * 16 * ROWB + ks * 32);
            #pragma unroll
            for (int np = 0; np < 2; np++) {
                uint32_t r0, r1, r2, r3;
                ldsm_x4(r0, r1, r2, r3, bT + np * 16 * ROWB + ks * 32);
                bf[np * 2][0] = r0; bf[np * 2][1] = r1;
                bf[np * 2 + 1][0] = r2; bf[np * 2 + 1][1] = r3;
            }
            #pragma unroll
            for (int mi = 0; mi < 4; mi++)
                #pragma unroll
                for (int ni = 0; ni < 4; ni++)
                    mma16816(acc[mi][ni], af[mi], bf[ni]);
        }
        __syncthreads();
    }

    // prefetch W1 pair 0 (panels 0,1 @ kc 0) -> slot 0
    #pragma unroll
    for (int pl = 0; pl < 2; pl++) {
        const __nv_bfloat16* Wg = w1 + (size_t)(pl * 128) * 256;
        #pragma unroll
        for (int it = 0; it < 4; it++) {
            int row = crow + it * 32;
            cp_async16(sW + pl * STG + row * ROWB + cch * 16,
                       Wg + (size_t)row * 256 + cch * 8);
        }
    }
    CP_COMMIT();

    // ---- epilogue GEMM1: x = embed + acc*mk -> out ; stats ----
    int qrow = lane >> 2, qcol = (lane & 3) * 2;
    #pragma unroll
    for (int mi = 0; mi < 4; mi++) {
        #pragma unroll
        for (int half = 0; half < 2; half++) {
            int rloc = mi * 16 + qrow + half * 8;
            size_t row = (size_t)m0 + rloc;
            float mk = (float)rmask[row];
            float s1 = 0.f, s2 = 0.f;
            #pragma unroll
            for (int ni = 0; ni < 4; ni++) {
                int c = wn * 32 + ni * 8 + qcol;
                float2 e = *(const float2*)(embed + row * 256 + c);
                float x0 = e.x + acc[mi][ni][half * 2 + 0] * mk;
                float x1 = e.y + acc[mi][ni][half * 2 + 1] * mk;
                acc[mi][ni][half * 2 + 0] = x0;
                acc[mi][ni][half * 2 + 1] = x1;
                *(float2*)(out + row * 256 + c) = make_float2(x0, x1);
                s1 += x0 + x1;
                s2 += x0 * x0 + x1 * x1;
            }
            s1 += __shfl_xor_sync(0xffffffffu, s1, 1);
            s1 += __shfl_xor_sync(0xffffffffu, s1, 2);
            s2 += __shfl_xor_sync(0xffffffffu, s2, 1);
            s2 += __shfl_xor_sync(0xffffffffu, s2, 2);
            if ((lane & 3) == 0) {
                sred[rloc * 8 + wn] = s1;
                sred[512 + rloc * 8 + wn] = s2;
            }
        }
    }
    __syncthreads();
    if (tid < 64) {
        float a1 = 0.f, a2 = 0.f;
        #pragma unroll
        for (int w = 0; w < 8; w++) {
            a1 += sred[tid * 8 + w];
            a2 += sred[512 + tid * 8 + w];
        }
        float mu = a1 * (1.f / 256.f);
        float var = a2 * (1.f / 256.f) - mu * mu;
        smu[tid] = mu;
        srs[tid] = rsqrtf(var + 1e-5f);
    }
    __syncthreads();
    // ---- LN -> hln in SMEM @0 ----
    #pragma unroll
    for (int mi = 0; mi < 4; mi++) {
        #pragma unroll
        for (int half = 0; half < 2; half++) {
            int rloc = mi * 16 + qrow + half * 8;
            float mu = smu[rloc], rs = srs[rloc];
            #pragma unroll
            for (int ni = 0; ni < 4; ni++) {
                int c = wn * 32 + ni * 8 + qcol;
                float h0 = (acc[mi][ni][half * 2 + 0] - mu) * rs * gam[c] + bet[c];
                float h1v = (acc[mi][ni][half * 2 + 1] - mu) * rs * gam[c + 1] + bet[c + 1];
                *(__nv_bfloat162*)(dsm + rloc * ROWH + c * 2) =
                    __floats2bfloat162_rn(h0, h1v);
            }
        }
    }

    // ---- GEMM2: h1 = relu(hln @ W1^T + b1); (panel-pair, kc) iterations ----
    float acc2[2][4][2][4];
    #pragma unroll
    for (int pl = 0; pl < 2; pl++)
        #pragma unroll
        for (int mi = 0; mi < 4; mi++)
            #pragma unroll
            for (int nf = 0; nf < 2; nf++)
                #pragma unroll
                for (int u = 0; u < 4; u++) acc2[pl][mi][nf][u] = 0.f;

    uint32_t a2_off = (uint32_t)((lrow + (grp & 1) * 8) * ROWH + (grp >> 1) * 16);

    #pragma unroll 1
    for (int g2 = 0; g2 < 8; g2++) {
        CP_WAIT(0);
        __syncthreads();
        if (g2 + 1 < 8) {
            int pp1 = (g2 + 1) >> 2, kc1 = (g2 + 1) & 3;
            uint32_t dst = sW + (uint32_t)((g2 + 1) & 1) * (2 * STG);
            #pragma unroll
            for (int pl = 0; pl < 2; pl++) {
                const __nv_bfloat16* Wg =
                    w1 + (size_t)((2 * pp1 + pl) * 128) * 256 + kc1 * 64;
                #pragma unroll
                for (int it = 0; it < 4; it++) {
                    int row = crow + it * 32;
                    cp_async16(dst + pl * STG + row * ROWB + cch * 16,
                               Wg + (size_t)row * 256 + cch * 8);
                }
            }
            CP_COMMIT();
        }

        int kc = g2 & 3;
        uint32_t slot = sW + (uint32_t)(g2 & 1) * (2 * STG);
        #pragma unroll
        for (int ks = 0; ks < 4; ks++) {
            uint32_t af[4][4];
            #pragma unroll
            for (int mi = 0; mi < 4; mi++)
                ldsm_x4(af[mi][0], af[mi][1], af[mi][2], af[mi][3],
                        sH + mi * 16 * ROWH + a2_off + kc * 128 + ks * 32);
            #pragma unroll
            for (int pl = 0; pl < 2; pl++) {
                uint32_t bk[4];
                ldsm_x4(bk[0], bk[1], bk[2], bk[3],
                        slot + pl * STG + (wn * 16) * ROWB + b_off + ks * 32);
                #pragma unroll
                for (int mi = 0; mi < 4; mi++) {
                    mma16816(acc2[pl][mi][0], af[mi], bk);
                    mma16816(acc2[pl][mi][1], af[mi], bk + 2);
                }
            }
        }

        if (kc == 3) {
            int pp = g2 >> 2;
            #pragma unroll
            for (int pl = 0; pl < 2; pl++) {
                int p = 2 * pp + pl;
                #pragma unroll
                for (int mi = 0; mi < 4; mi++)
                    #pragma unroll
                    for (int half = 0; half < 2; half++) {
                        size_t row = (size_t)m0 + mi * 16 + qrow + half * 8;
                        #pragma unroll
                        for (int nf = 0; nf < 2; nf++) {
                            int c = p * 128 + wn * 16 + nf * 8 + qcol;
                            float r0 = fmaxf(acc2[pl][mi][nf][half * 2 + 0] + b1[c], 0.f);
                            float r1 = fmaxf(acc2[pl][mi][nf][half * 2 + 1] + b1[c + 1], 0.f);
                            *(__nv_bfloat162*)(h1 + row * 512 + c) =
                                __floats2bfloat162_rn(r0, r1);
                            acc2[pl][mi][nf][half * 2 + 0] = 0.f;
                            acc2[pl][mi][nf][half * 2 + 1] = 0.f;
                        }
                    }
            }
        }
    }
}

// ============ combined weight-transpose + both input LayerNorms =============
__device__ __forceinline__ void wt_seg(const float* W, __nv_bfloat16* Wt,
                                       int idx, int N, int K) {
    int k = idx / N, n = idx % N;
    Wt[(size_t)n * K + k] = __float2bfloat16(W[idx]);
}
__device__ __forceinline__ void ln_token(
    const float* __restrict__ xr, const float* __restrict__ gam,
    const float* __restrict__ bet, __nv_bfloat16* __restrict__ yr, int lane)
{
    const float2* x2 = (const float2*)xr;
    float2 v[4];
    #pragma unroll
    for (int u = 0; u < 4; u++) v[u] = x2[lane + 32 * u];
    float s = 0.f;
    #pragma unroll
    for (int u = 0; u < 4; u++) s += v[u].x + v[u].y;
    #pragma unroll
    for (int o = 16; o; o >>= 1) s += __shfl_xor_sync(0xffffffffu, s, o);
    float mu = s * (1.f / 256.f);
    float ss = 0.f;
    float2 d[4];
    #pragma unroll
    for (int u = 0; u < 4; u++) {
        d[u].x = v[u].x - mu; d[u].y = v[u].y - mu;
        ss += d[u].x * d[u].x + d[u].y * d[u].y;
    }
    #pragma unroll
    for (int o = 16; o; o >>= 1) ss += __shfl_xor_sync(0xffffffffu, ss, o);
    float r = rsqrtf(ss * (1.f / 256.f) + 1e-5f);
    const float2* g2 = (const float2*)gam;
    const float2* b2 = (const float2*)bet;
    __nv_bfloat162* y2 = (__nv_bfloat162*)yr;
    #pragma unroll
    for (int u = 0; u < 4; u++) {
        int c2 = lane + 32 * u;
        float2 g = g2[c2], b = b2[c2];
        y2[c2] = __floats2bfloat162_rn(d[u].x * r * g.x + b.x,
                                       d[u].y * r * g.y + b.y);
    }
}

#define LN_BLOCKS ((MQ + MK) / 8)   /* 15360 */
__global__ __launch_bounds__(256) void prep_kernel(
    const float* __restrict__ embed, const float* __restrict__ memory,
    const float* __restrict__ sq, const float* __restrict__ bq,
    const float* __restrict__ skv, const float* __restrict__ bkv,
    __nv_bfloat16* __restrict__ qe, __nv_bfloat16* __restrict__ km,
    const float* __restrict__ Wq, const float* __restrict__ Wgate,
    const float* __restrict__ Wkv, const float* __restrict__ Wout,
    const float* __restrict__ W1, const float* __restrict__ W2,
    __nv_bfloat16* __restrict__ wqg, __nv_bfloat16* __restrict__ wkv,
    __nv_bfloat16* __restrict__ wo, __nv_bfloat16* __restrict__ w1,
    __nv_bfloat16* __restrict__ w2)
{
    if (blockIdx.x < LN_BLOCKS) {
        int gw   = (blockIdx.x * 256 + threadIdx.x) >> 5;
        int lane = threadIdx.x & 31;
        if (gw < MQ) {
            ln_token(embed + (size_t)gw * 256, sq, bq, qe + (size_t)gw * 256, lane);
        } else {
            size_t t = gw - MQ;
            ln_token(memory + t * 256, skv, bkv, km + t * 256, lane);
        }
    } else {
        int idx = (blockIdx.x - LN_BLOCKS) * 256 + threadIdx.x;
        if (idx < 65536)                { wt_seg(Wq,    wqg,         idx,          256, 256); return; }
        if (idx < 2*65536)              { wt_seg(Wgate, wqg + 65536, idx - 65536,  256, 256); return; }
        if (idx < 2*65536 + 131072)     { wt_seg(Wkv,   wkv,         idx - 131072, 512, 256); return; }
        if (idx < 3*65536 + 131072)     { wt_seg(Wout,  wo,          idx - 262144, 256, 256); return; }
        if (idx < 3*65536 + 2*131072)   { wt_seg(W1,    w1,          idx - 327680, 512, 256); return; }
        if (idx < 3*65536 + 3*131072)   { wt_seg(W2,    w2,          idx - 458752, 256, 512); return; }
    }
}

// =============== MMA attention v5 (head-axis softmax) =======================
// v5: Q smem tile eliminated — A fragments loaded directly from gmem (the
//     m16n8k16 A layout is plain-addressable). smem 71->54 KB => 4 CTAs/SM.
#define ROWQ 528
#define KVBUF (2 * 32 * ROWQ)
#define PB_PLANE 2560
#define SMEM_ATT (KVBUF + 8 * PB_PLANE)   /* 54272 */
__global__ __launch_bounds__(256, 4) void attention_mma_kernel(
    const __nv_bfloat16* __restrict__ qg,
    const __nv_bfloat16* __restrict__ kv,
    const int*  __restrict__ rmask,
    const int*  __restrict__ mmask,
    __nv_bfloat16* __restrict__ out)
{
    extern __shared__ char sm8[];
    const uint32_t sK = smem_u32(sm8);
    const uint32_t sV = sK + 32 * ROWQ;
    const uint32_t sP = sK + KVBUF;
    char* Pb = sm8 + KVBUF;
    __shared__ float rm[32];
    __shared__ float mb6[64];

    int n = blockIdx.x, i0 = blockIdx.y * 32;
    int tid = threadIdx.x, lane = tid & 31, h = tid >> 5;
    int lrow = lane & 7, grp = lane >> 3;

    if (tid < 64) mb6[tid] = (float)mmask[tid * N_DIM + n] * 1e6f;
    if (tid < 32) rm[tid] = (float)rmask[(i0 + tid) * N_DIM + n];

    // base pointer for this thread's Q fragments: row (i0 + lane>>2), head h,
    // k element 2*(lane&3). Fragment (mi, ks) offsets added per use.
    const size_t RSTR = (size_t)N_DIM * 512;   // token row stride in elements
    const __nv_bfloat16* qfb =
        qg + ((size_t)(i0 + (lane >> 2)) * N_DIM + n) * 512
           + h * 32 + 2 * (lane & 3);

    // phase-0 K/V
    #pragma unroll
    for (int it = 0; it < 8; it++) {
        int idx = tid + it * 256;
        int row = idx >> 6, c = idx & 63;
        uint32_t dst = (c < 32) ? (sK + row * ROWQ + c * 16)
                                : (sV + row * ROWQ + (c - 32) * 16);
        cp_async16(dst, kv + ((size_t)row * N_DIM + n) * 512 + c * 8);
    }
    CP_COMMIT();

    float acc_o[2][4][4];
    #pragma unroll
    for (int mi = 0; mi < 2; mi++)
        #pragma unroll
        for (int nb = 0; nb < 4; nb++)
            #pragma unroll
            for (int e = 0; e < 4; e++) acc_o[mi][nb][e] = 0.f;

    CP_WAIT(0);
    __syncthreads();

    #pragma unroll 1
    for (int ph = 0; ph < 2; ph++) {
        float acc_s[2][4][4];
        #pragma unroll
        for (int mi = 0; mi < 2; mi++)
            #pragma unroll
            for (int jb = 0; jb < 4; jb++)
                #pragma unroll
                for (int e = 0; e < 4; e++) acc_s[mi][jb][e] = 0.f;

        #pragma unroll
        for (int ks = 0; ks < 2; ks++) {
            uint32_t aq[2][4];
            #pragma unroll
            for (int mi = 0; mi < 2; mi++) {
                const __nv_bfloat16* fb = qfb + (size_t)(mi * 16) * RSTR + ks * 16;
                aq[mi][0] = *(const uint32_t*)(fb);
                aq[mi][1] = *(const uint32_t*)(fb + 8 * RSTR);
                aq[mi][2] = *(const uint32_t*)(fb + 8);
                aq[mi][3] = *(const uint32_t*)(fb + 8 * RSTR + 8);
            }
            #pragma unroll
            for (int jbp = 0; jbp < 2; jbp++) {
                uint32_t bk[4];
                ldsm_x4(bk[0], bk[1], bk[2], bk[3],
                        sK + (jbp * 16 + lrow + (grp >> 1) * 8) * ROWQ
                           + h * 64 + ks * 32 + (grp & 1) * 16);
                #pragma unroll
                for (int mi = 0; mi < 2; mi++) {
                    mma16816(acc_s[mi][jbp * 2],     aq[mi], bk);
                    mma16816(acc_s[mi][jbp * 2 + 1], aq[mi], bk + 2);
                }
            }
        }

        #pragma unroll
        for (int mi = 0; mi < 2; mi++)
            #pragma unroll
            for (int jb = 0; jb < 4; jb++)
                #pragma unroll
                for (int half = 0; half < 2; half++) {
                    int i = mi * 16 + (lane >> 2) + half * 8;
                    int j = jb * 8 + (lane & 3) * 2;
                    float b0 = fmaf(rm[i], mb6[ph * 32 + j],     -1e6f);
                    float b1 = fmaf(rm[i], mb6[ph * 32 + j + 1], -1e6f);
                    float p0 = __expf((acc_s[mi][jb][half * 2 + 0] + b0) - b0);
                    float p1 = __expf((acc_s[mi][jb][half * 2 + 1] + b1) - b1);
                    *(__nv_bfloat162*)(Pb + h * PB_PLANE + i * 80 + j * 2) =
                        __floats2bfloat162_rn(p0, p1);
                }
        __syncthreads();   // exp visible; all warps done reading K

        if (ph == 0) {
            #pragma unroll
            for (int it = 0; it < 4; it++) {
                int idx = tid + it * 256;
                int row = idx >> 5, c = idx & 31;
                cp_async16(sK + row * ROWQ + c * 16,
                           kv + ((size_t)(32 + row) * N_DIM + n) * 512 + c * 8);
            }
            CP_COMMIT();
        }

        #pragma unroll
        for (int t = 0; t < 2; t++) {
            int idx = tid + t * 256;
            int i = idx >> 4, jp = idx & 15;
            char* base = Pb + i * 80 + jp * 4;
            float2 pv[8];
            float s0 = 0.f, s1 = 0.f;
            #pragma unroll
            for (int hh = 0; hh < 8; hh++) {
                pv[hh] = __bfloat1622float2(
                    *(const __nv_bfloat162*)(base + hh * PB_PLANE));
                s0 += pv[hh].x;
                s1 += pv[hh].y;
            }
            float inv0 = __fdividef(1.f, s0);
            float inv1 = __fdividef(1.f, s1);
            #pragma unroll
            for (int hh = 0; hh < 8; hh++)
                *(__nv_bfloat162*)(base + hh * PB_PLANE) =
                    __floats2bfloat162_rn(pv[hh].x * inv0, pv[hh].y * inv1);
        }
        if (ph == 1) CP_WAIT(0);
        __syncthreads();

        #pragma unroll
        for (int ks = 0; ks < 2; ks++) {
            uint32_t ap[2][4];
            #pragma unroll
            for (int mi = 0; mi < 2; mi++)
                ldsm_x4(ap[mi][0], ap[mi][1], ap[mi][2], ap[mi][3],
                        sP + h * PB_PLANE + (mi * 16 + lrow + (grp & 1) * 8) * 80
                           + ks * 32 + (grp >> 1) * 16);
            #pragma unroll
            for (int cb = 0; cb < 2; cb++) {
                uint32_t bv[4];
                ldsm_x4_trans(bv[0], bv[1], bv[2], bv[3],
                        sV + (ks * 16 + lrow + (grp & 1) * 8) * ROWQ
                           + h * 64 + cb * 32 + (grp >> 1) * 16);
                #pragma unroll
                for (int mi = 0; mi < 2; mi++) {
                    mma16816(acc_o[mi][cb * 2],     ap[mi], bv);
                    mma16816(acc_o[mi][cb * 2 + 1], ap[mi], bv + 2);
                }
            }
        }
        __syncthreads();

        if (ph == 0) {
            #pragma unroll
            for (int it = 0; it < 4; it++) {
                int idx = tid + it * 256;
                int row = idx >> 5, c = idx & 31;
                cp_async16(sV + row * ROWQ + c * 16,
                           kv + ((size_t)(32 + row) * N_DIM + n) * 512
                              + 256 + c * 8);
            }
            CP_COMMIT();
            CP_WAIT(1);
            __syncthreads();
        }
    }

    #pragma unroll
    for (int mi = 0; mi < 2; mi++)
        #pragma unroll
        for (int half = 0; half < 2; half++) {
            size_t R = (size_t)(i0 + mi * 16 + (lane >> 2) + half * 8);
            const __nv_bfloat16* gp = qg + (R * N_DIM + n) * 512 + 256 + h * 32;
            __nv_bfloat16* op = out + (R * N_DIM + n) * 256 + h * 32;
            #pragma unroll
            for (int nb = 0; nb < 4; nb++) {
                int ch = nb * 8 + (lane & 3) * 2;
                __nv_bfloat162 g = *(const __nv_bfloat162*)(gp + ch);
                float gx = __bfloat162float(g.x), gy = __bfloat162float(g.y);
                float r0 = acc_o[mi][nb][half * 2 + 0]
                           * __fdividef(1.f, 1.f + __expf(-gx));
                float r1 = acc_o[mi][nb][half * 2 + 1]
                           * __fdividef(1.f, 1.f + __expf(-gy));
                *(__nv_bfloat162*)(op + ch) = __floats2bfloat162_rn(r0, r1);
            }
        }
}

// ---------------- launch -----------------------------------------------------
extern "C" void kernel_launch(void* const* d_in, const int* in_sizes, int n_in,
                              void* d_out, int out_size)
{
    const float* embed   = (const float*)d_in[0];
    const float* memory  = (const float*)d_in[1];
    const int*   rmask   = (const int*)  d_in[2];
    const int*   mmask   = (const int*)  d_in[3];
    const float* ln_q_s  = (const float*)d_in[4];
    const float* ln_q_b  = (const float*)d_in[5];
    const float* ln_kv_s = (const float*)d_in[6];
    const float* ln_kv_b = (const float*)d_in[7];
    const float* Wq      = (const float*)d_in[8];
    const float* Wkv     = (const float*)d_in[9];
    const float* Wgate   = (const float*)d_in[10];
    const float* Wout    = (const float*)d_in[11];
    const float* ln_f_s  = (const float*)d_in[12];
    const float* ln_f_b  = (const float*)d_in[13];
    const float* W1      = (const float*)d_in[14];
    const float* b1      = (const float*)d_in[15];
    const float* W2      = (const float*)d_in[16];
    const float* b2      = (const float*)d_in[17];
    float* out = (float*)d_out;

    __nv_bfloat16 *qe, *km, *qgb, *kvb, *ab, *h1;
    __nv_bfloat16 *wqg, *wkv, *wo, *w1, *w2;
    cudaGetSymbolAddress((void**)&qe,  g_qe);
    cudaGetSymbolAddress((void**)&km,  g_km);
    cudaGetSymbolAddress((void**)&qgb, g_qg);
    cudaGetSymbolAddress((void**)&kvb, g_kv);
    cudaGetSymbolAddress((void**)&ab,  g_ab);
    cudaGetSymbolAddress((void**)&h1,  g_h1);
    cudaGetSymbolAddress((void**)&wqg, g_Wqg);
    cudaGetSymbolAddress((void**)&wkv, g_Wkv);
    cudaGetSymbolAddress((void**)&wo,  g_Wo);
    cudaGetSymbolAddress((void**)&w1,  g_W1);
    cudaGetSymbolAddress((void**)&w2,  g_W2);

    const int SMEM_GEMM = 4 * STG;
    cudaFuncSetAttribute(qgkv_gemm,            cudaFuncAttributeMaxDynamicSharedMemorySize, SMEM_BRES);
    cudaFuncSetAttribute(mma_gemm<3, false>,   cudaFuncAttributeMaxDynamicSharedMemorySize, SMEM_GEMM);
    cudaFuncSetAttribute(gemm_ln_ffn1_kernel,  cudaFuncAttributeMaxDynamicSharedMemorySize, SMEM_GLN);
    cudaFuncSetAttribute(attention_mma_kernel, cudaFuncAttributeMaxDynamicSharedMemorySize, SMEM_ATT);

    // idx 0: combined LN(inputs) + all weight transposes
    prep_kernel<<<LN_BLOCKS + (589824 + 255) / 256, 256>>>(
        embed, memory, ln_q_s, ln_q_b, ln_kv_s, ln_kv_b, qe, km,
        Wq, Wgate, Wkv, Wout, W1, W2, wqg, wkv, wo, w1, w2);
    // idx 1: q|gate (z=0) and kv (z=1) projections
    qgkv_gemm<<<dim3(4, 192, 2), 256, SMEM_BRES>>>(qe, wqg, qgb, km, wkv, kvb);
    // idx 2: MMA attention + sigmoid gating (4 CTAs/SM)
    attention_mma_kernel<<<dim3(N_DIM, 8), 256, SMEM_ATT>>>(qgb, kvb,
                                                            rmask, mmask, ab);
    // idx 3: fused x=embed+(ab@Wo)*rmask -> out ; LN ; h1 (PROFILED)
    gemm_ln_ffn1_kernel<<<MQ / 64, 256, SMEM_GLN>>>(ab, wo, embed, rmask,
                                                    ln_f_s, ln_f_b, w1, b1,
                                                    out, h1);
    // idx 4: FFN2
    mma_gemm<3, false><<<dim3(2, MQ / 128), 256, SMEM_GEMM>>>(
        h1, w2, out, 256, 512, b2, out, rmask);
}

// round 17
// speedup vs baseline: 1.0485x; 1.0485x over previous
#include <cuda_runtime.h>
#include <cuda_bf16.h>
#include <cstdint>
#include <cstddef>

#define I_DIM 256
#define J_DIM 64
#define N_DIM 384
#define MQ (I_DIM * N_DIM)   /* 98304 query tokens  */
#define MK (J_DIM * N_DIM)   /* 24576 memory tokens */

// ---------------- scratch (device globals; no allocations allowed) ----------
__device__ __nv_bfloat16 g_qe [(size_t)MQ * 256];   // LN(embed) bf16
__device__ __nv_bfloat16 g_km [(size_t)MK * 256];   // LN(memory) bf16
__device__ __nv_bfloat16 g_qg [(size_t)MQ * 512];   // [q | gate] bf16
__device__ __nv_bfloat16 g_kv [(size_t)MK * 512];   // km @ Wkv bf16
__device__ __nv_bfloat16 g_ab [(size_t)MQ * 256];   // gated attention out bf16
__device__ __nv_bfloat16 g_h1 [(size_t)MQ * 512];   // relu FFN hidden bf16
// transposed bf16 weights: Wt[n][k] = W[k][n]
__device__ __nv_bfloat16 g_Wqg[512 * 256];          // rows 0-255 Wq, 256-511 Wgate
__device__ __nv_bfloat16 g_Wkv[512 * 256];
__device__ __nv_bfloat16 g_Wo [256 * 256];
__device__ __nv_bfloat16 g_W1 [512 * 256];
__device__ __nv_bfloat16 g_W2 [256 * 512];

// ======================= sm_80-baseline PTX helpers =========================
__device__ __forceinline__ uint32_t smem_u32(const void* p) {
    uint32_t a;
    asm("{ .reg .u64 t; cvta.to.shared.u64 t, %1; cvt.u32.u64 %0, t; }"
        : "=r"(a) : "l"(p));
    return a;
}
__device__ __forceinline__ void cp_async16(uint32_t saddr, const void* gaddr) {
    asm volatile("cp.async.cg.shared.global [%0], [%1], 16;"
                 :: "r"(saddr), "l"(gaddr) : "memory");
}
#define CP_COMMIT() asm volatile("cp.async.commit_group;" ::: "memory")
#define CP_WAIT(n)  asm volatile("cp.async.wait_group %0;" :: "n"(n) : "memory")

__device__ __forceinline__ void ldsm_x4(uint32_t& r0, uint32_t& r1,
                                        uint32_t& r2, uint32_t& r3, uint32_t addr) {
    asm volatile("ldmatrix.sync.aligned.m8n8.x4.shared.b16 {%0,%1,%2,%3}, [%4];"
                 : "=r"(r0), "=r"(r1), "=r"(r2), "=r"(r3) : "r"(addr));
}
__device__ __forceinline__ void ldsm_x4_trans(uint32_t& r0, uint32_t& r1,
                                              uint32_t& r2, uint32_t& r3, uint32_t addr) {
    asm volatile("ldmatrix.sync.aligned.m8n8.x4.trans.shared.b16 {%0,%1,%2,%3}, [%4];"
                 : "=r"(r0), "=r"(r1), "=r"(r2), "=r"(r3) : "r"(addr));
}
__device__ __forceinline__ void mma16816(float* d, const uint32_t* a, const uint32_t* b) {
    asm volatile("mma.sync.aligned.m16n8k16.row.col.f32.bf16.bf16.f32 "
                 "{%0,%1,%2,%3}, {%4,%5,%6,%7}, {%8,%9}, {%0,%1,%2,%3};"
                 : "+f"(d[0]), "+f"(d[1]), "+f"(d[2]), "+f"(d[3])
                 : "r"(a[0]), "r"(a[1]), "r"(a[2]), "r"(a[3]),
                   "r"(b[0]), "r"(b[1]));
}

#define ROWB 144
#define STG  (128 * ROWB)

// ======== B-resident GEMM (K=256): B panel lives in smem; CTA loops m =======
#define SMEM_BRES (6 * STG)
template <int EPI, bool OUTBF, int MB>
__device__ __forceinline__ void gemm_bres_body(
    char* dsm, const __nv_bfloat16* __restrict__ A,
    const __nv_bfloat16* __restrict__ Bt, void* __restrict__ Cout,
    int Ntot, const float* __restrict__ bias, int n0, int m0_base)
{
    const uint32_t sB = smem_u32(dsm);
    const uint32_t sA = sB + 4 * STG;
    int tid = threadIdx.x, lane = tid & 31, wid = tid >> 5;
    int wm = wid >> 2, wn = wid & 3;
    int crow = tid >> 3, cch = tid & 7;
    int lrow = lane & 7, grp = lane >> 3;
    uint32_t a_off = (uint32_t)((lrow + (grp & 1) * 8) * ROWB + (grp >> 1) * 16);
    uint32_t b_off = (uint32_t)((lrow + (grp >> 1) * 8) * ROWB + (grp & 1) * 16);

    const __nv_bfloat16* Bg = Bt + (size_t)n0 * 256;
    #pragma unroll
    for (int kc = 0; kc < 4; kc++)
        #pragma unroll
        for (int it = 0; it < 4; it++) {
            int row = crow + it * 32;
            cp_async16(sB + kc * STG + row * ROWB + cch * 16,
                       Bg + (size_t)row * 256 + kc * 64 + cch * 8);
        }
    CP_COMMIT();
    {
        const __nv_bfloat16* Ag = A + (size_t)m0_base * 256;
        #pragma unroll
        for (int it = 0; it < 4; it++) {
            int row = crow + it * 32;
            cp_async16(sA + row * ROWB + cch * 16, Ag + (size_t)row * 256 + cch * 8);
        }
    }
    CP_COMMIT();
    CP_WAIT(0);
    __syncthreads();

    float acc[4][4][4];
    #pragma unroll
    for (int i = 0; i < 4; i++)
        #pragma unroll
        for (int j = 0; j < 4; j++)
            #pragma unroll
            for (int u = 0; u < 4; u++) acc[i][j][u] = 0.f;

    const int TOT = MB * 4;
    #pragma unroll 1
    for (int g = 0; g < TOT; g++) {
        int cur = g & 1;
        if (g + 1 < TOT) {
            int g1 = g + 1;
            int mb1 = g1 >> 2, kc1 = g1 & 3;
            const __nv_bfloat16* Agn =
                A + ((size_t)m0_base + (size_t)mb1 * 192 * 128) * 256 + kc1 * 64;
            #pragma unroll
            for (int it = 0; it < 4; it++) {
                int row = crow + it * 32;
                cp_async16(sA + (g1 & 1) * STG + row * ROWB + cch * 16,
                           Agn + (size_t)row * 256 + cch * 8);
            }
            CP_COMMIT();
            CP_WAIT(1);
        } else {
            CP_WAIT(0);
        }
        __syncthreads();

        int kc = g & 3;
        uint32_t aT = sA + cur * STG + (wm * 64) * ROWB + a_off;
        uint32_t bT = sB + kc * STG + (wn * 32) * ROWB + b_off;
        #pragma unroll
        for (int ks = 0; ks < 4; ks++) {
            uint32_t af[4][4], bf[4][2];
            #pragma unroll
            for (int mi = 0; mi < 4; mi++)
                ldsm_x4(af[mi][0], af[mi][1], af[mi][2], af[mi][3],
                        aT + mi * 16 * ROWB + ks * 32);
            #pragma unroll
            for (int np = 0; np < 2; np++) {
                uint32_t r0, r1, r2, r3;
                ldsm_x4(r0, r1, r2, r3, bT + np * 16 * ROWB + ks * 32);
                bf[np * 2][0] = r0; bf[np * 2][1] = r1;
                bf[np * 2 + 1][0] = r2; bf[np * 2 + 1][1] = r3;
            }
            #pragma unroll
            for (int mi = 0; mi < 4; mi++)
                #pragma unroll
                for (int ni = 0; ni < 4; ni++)
                    mma16816(acc[mi][ni], af[mi], bf[ni]);
        }
        __syncthreads();

        if (kc == 3) {
            size_t m0 = (size_t)m0_base + (size_t)(g >> 2) * 192 * 128;
            int qrow = lane >> 2, qcol = (lane & 3) * 2;
            #pragma unroll
            for (int mi = 0; mi < 4; mi++) {
                #pragma unroll
                for (int half = 0; half < 2; half++) {
                    size_t row = m0 + wm * 64 + mi * 16 + qrow + half * 8;
                    #pragma unroll
                    for (int ni = 0; ni < 4; ni++) {
                        int c = n0 + wn * 32 + ni * 8 + qcol;
                        float r0 = acc[mi][ni][half * 2 + 0];
                        float r1 = acc[mi][ni][half * 2 + 1];
                        if (EPI == 1) {
                            r0 = fmaxf(r0 + bias[c], 0.f);
                            r1 = fmaxf(r1 + bias[c + 1], 0.f);
                        }
                        if (OUTBF) {
                            *(__nv_bfloat162*)((__nv_bfloat16*)Cout + row * Ntot + c)
                                = __floats2bfloat162_rn(r0, r1);
                        } else {
                            *(float2*)((float*)Cout + row * Ntot + c) =
                                make_float2(r0, r1);
                        }
                        acc[mi][ni][half * 2 + 0] = 0.f;
                        acc[mi][ni][half * 2 + 1] = 0.f;
                    }
                }
            }
        }
    }
}

// combined q|gate (z=0, 4 m-blocks) + kv (z=1, 1 m-block) projection
__global__ __launch_bounds__(256) void qgkv_gemm(
    const __nv_bfloat16* __restrict__ qe, const __nv_bfloat16* __restrict__ wqg,
    __nv_bfloat16* __restrict__ qgb,
    const __nv_bfloat16* __restrict__ km, const __nv_bfloat16* __restrict__ wkv,
    __nv_bfloat16* __restrict__ kvb)
{
    extern __shared__ char dsm[];
    if (blockIdx.z == 0) {
        gemm_bres_body<0, true, 4>(dsm, qe, wqg, qgb, 512, nullptr,
                                   blockIdx.x * 128, blockIdx.y * 128);
    } else {
        gemm_bres_body<0, true, 1>(dsm, km, wkv, kvb, 512, nullptr,
                                   blockIdx.x * 128, blockIdx.y * 128);
    }
}

// ============ classic double-buffer GEMM (used for FFN2) ====================
template <int EPI, bool OUTBF>
__global__ __launch_bounds__(256) void mma_gemm(
    const __nv_bfloat16* __restrict__ A, const __nv_bfloat16* __restrict__ Bt,
    void* __restrict__ Cout, int Ntot, int Ktot,
    const float* __restrict__ bias, const float* __restrict__ resid,
    const int* __restrict__ rmask)
{
    extern __shared__ char dsm[];
    const uint32_t sA = smem_u32(dsm);
    const uint32_t sB = sA + 2 * STG;
    int tid = threadIdx.x, lane = tid & 31, wid = tid >> 5;
    int wm = wid >> 2, wn = wid & 3;
    int n0 = blockIdx.x * 128, m0 = blockIdx.y * 128;

    const __nv_bfloat16* Ag = A  + (size_t)m0 * Ktot;
    const __nv_bfloat16* Bg = Bt + (size_t)n0 * Ktot;

    int crow = tid >> 3, cch = tid & 7;
    int lrow = lane & 7, grp = lane >> 3;
    uint32_t a_off = (uint32_t)((lrow + (grp & 1) * 8) * ROWB + (grp >> 1) * 16);
    uint32_t b_off = (uint32_t)((lrow + (grp >> 1) * 8) * ROWB + (grp & 1) * 16);

    float acc[4][4][4];
    #pragma unroll
    for (int i = 0; i < 4; i++)
        #pragma unroll
        for (int j = 0; j < 4; j++)
            #pragma unroll
            for (int u = 0; u < 4; u++) acc[i][j][u] = 0.f;

    const int NC = Ktot >> 6;

    #pragma unroll
    for (int it = 0; it < 4; it++) {
        int row = crow + it * 32;
        cp_async16(sA + row * ROWB + cch * 16, Ag + (size_t)row * Ktot + cch * 8);
        cp_async16(sB + row * ROWB + cch * 16, Bg + (size_t)row * Ktot + cch * 8);
    }
    CP_COMMIT();

    for (int kc = 0; kc < NC; kc++) {
        int cur = kc & 1;
        if (kc + 1 < NC) {
            int nxt = cur ^ 1;
            const __nv_bfloat16* Agn = Ag + (kc + 1) * 64;
            const __nv_bfloat16* Bgn = Bg + (kc + 1) * 64;
            #pragma unroll
            for (int it = 0; it < 4; it++) {
                int row = crow + it * 32;
                cp_async16(sA + nxt * STG + row * ROWB + cch * 16,
                           Agn + (size_t)row * Ktot + cch * 8);
                cp_async16(sB + nxt * STG + row * ROWB + cch * 16,
                           Bgn + (size_t)row * Ktot + cch * 8);
            }
            CP_COMMIT();
            CP_WAIT(1);
        } else {
            CP_WAIT(0);
        }
        __syncthreads();

        uint32_t aT = sA + cur * STG + (wm * 64) * ROWB + a_off;
        uint32_t bT = sB + cur * STG + (wn * 32) * ROWB + b_off;
        #pragma unroll
        for (int ks = 0; ks < 4; ks++) {
            uint32_t af[4][4], bf[4][2];
            #pragma unroll
            for (int mi = 0; mi < 4; mi++)
                ldsm_x4(af[mi][0], af[mi][1], af[mi][2], af[mi][3],
                        aT + mi * 16 * ROWB + ks * 32);
            #pragma unroll
            for (int np = 0; np < 2; np++) {
                uint32_t r0, r1, r2, r3;
                ldsm_x4(r0, r1, r2, r3, bT + np * 16 * ROWB + ks * 32);
                bf[np * 2][0] = r0; bf[np * 2][1] = r1;
                bf[np * 2 + 1][0] = r2; bf[np * 2 + 1][1] = r3;
            }
            #pragma unroll
            for (int mi = 0; mi < 4; mi++)
                #pragma unroll
                for (int ni = 0; ni < 4; ni++)
                    mma16816(acc[mi][ni], af[mi], bf[ni]);
        }
        __syncthreads();
    }

    int qrow = lane >> 2, qcol = (lane & 3) * 2;
    #pragma unroll
    for (int mi = 0; mi < 4; mi++) {
        #pragma unroll
        for (int half = 0; half < 2; half++) {
            size_t row = (size_t)m0 + wm * 64 + mi * 16 + qrow + half * 8;
            float mk = 1.f;
            if (EPI >= 2) mk = (float)rmask[row];
            #pragma unroll
            for (int ni = 0; ni < 4; ni++) {
                int c = n0 + wn * 32 + ni * 8 + qcol;
                float r0 = acc[mi][ni][half * 2 + 0];
                float r1 = acc[mi][ni][half * 2 + 1];
                if (EPI == 1) {
                    r0 = fmaxf(r0 + bias[c], 0.f);
                    r1 = fmaxf(r1 + bias[c + 1], 0.f);
                } else if (EPI == 3) {
                    const float* rp = resid + row * Ntot + c;
                    r0 = rp[0] + (r0 + bias[c]) * mk;
                    r1 = rp[1] + (r1 + bias[c + 1]) * mk;
                }
                if (OUTBF) {
                    *(__nv_bfloat162*)((__nv_bfloat16*)Cout + row * Ntot + c) =
                        __floats2bfloat162_rn(r0, r1);
                } else {
                    *(float2*)((float*)Cout + row * Ntot + c) = make_float2(r0, r1);
                }
            }
        }
    }
}

// ======= fused: Wout-GEMM + residual + FFN-LN + FFN1 (h1) ===================
#define STG_A64 (64 * ROWB)
#define STG_B256 (256 * ROWB)
#define ROWH 528
#define GLF_W   33792                       /* 2 pair-slots of 36864 */
#define GLF_RED 107520
#define SMEM_GLN (GLF_RED + 1024 * 4 + 128 * 4)  /* 112128 */
__global__ __launch_bounds__(256, 2) void gemm_ln_ffn1_kernel(
    const __nv_bfloat16* __restrict__ A, const __nv_bfloat16* __restrict__ Bt,
    const float* __restrict__ embed, const int* __restrict__ rmask,
    const float* __restrict__ gam, const float* __restrict__ bet,
    const __nv_bfloat16* __restrict__ w1, const float* __restrict__ b1,
    float* __restrict__ out, __nv_bfloat16* __restrict__ h1)
{
    extern __shared__ char dsm[];
    const uint32_t sA = smem_u32(dsm);
    const uint32_t sB = sA + 2 * STG_A64;
    const uint32_t sH = sA;                  // hln overlays sA/sB after GEMM1
    const uint32_t sW = sA + GLF_W;
    float* sred = (float*)(dsm + GLF_RED);
    float* smu  = sred + 1024;
    float* srs  = smu + 64;
    int tid = threadIdx.x, lane = tid & 31, wn = tid >> 5;
    int m0 = blockIdx.x * 64;

    const __nv_bfloat16* Ag = A + (size_t)m0 * 256;
    const __nv_bfloat16* Bg = Bt;

    int crow = tid >> 3, cch = tid & 7;
    int lrow = lane & 7, grp = lane >> 3;
    uint32_t a_off = (uint32_t)((lrow + (grp & 1) * 8) * ROWB + (grp >> 1) * 16);
    uint32_t b_off = (uint32_t)((lrow + (grp >> 1) * 8) * ROWB + (grp & 1) * 16);

    float acc[4][4][4];
    #pragma unroll
    for (int i = 0; i < 4; i++)
        #pragma unroll
        for (int j = 0; j < 4; j++)
            #pragma unroll
            for (int u = 0; u < 4; u++) acc[i][j][u] = 0.f;

    #pragma unroll
    for (int it = 0; it < 2; it++) {
        int row = crow + it * 32;
        cp_async16(sA + row * ROWB + cch * 16, Ag + (size_t)row * 256 + cch * 8);
    }
    #pragma unroll
    for (int it = 0; it < 8; it++) {
        int row = crow + it * 32;
        cp_async16(sB + row * ROWB + cch * 16, Bg + (size_t)row * 256 + cch * 8);
    }
    CP_COMMIT();

    for (int kc = 0; kc < 4; kc++) {
        int cur = kc & 1;
        if (kc + 1 < 4) {
            int nxt = cur ^ 1;
            const __nv_bfloat16* Agn = Ag + (kc + 1) * 64;
            const __nv_bfloat16* Bgn = Bg + (kc + 1) * 64;
            #pragma unroll
            for (int it = 0; it < 2; it++) {
                int row = crow + it * 32;
                cp_async16(sA + nxt * STG_A64 + row * ROWB + cch * 16,
                           Agn + (size_t)row * 256 + cch * 8);
            }
            #pragma unroll
            for (int it = 0; it < 8; it++) {
                int row = crow + it * 32;
                cp_async16(sB + nxt * STG_B256 + row * ROWB + cch * 16,
                           Bgn + (size_t)row * 256 + cch * 8);
            }
            CP_COMMIT();
            CP_WAIT(1);
        } else {
            CP_WAIT(0);
        }
        __syncthreads();

        uint32_t aT = sA + cur * STG_A64 + a_off;
        uint32_t bT = sB + cur * STG_B256 + (wn * 32) * ROWB + b_off;
        #pragma unroll
        for (int ks = 0; ks < 4; ks++) {
            uint32_t af[4][4], bf[4][2];
            #pragma unroll
            for (int mi = 0; mi < 4; mi++)
                ldsm_x4(af[mi][0], af[mi][1], af[mi][2], af[mi][3],
                        aT + mi * 16 * ROWB + ks * 32);
            #pragma unroll
            for (int np = 0; np < 2; np++) {
                uint32_t r0, r1, r2, r3;
                ldsm_x4(r0, r1, r2, r3, bT + np * 16 * ROWB + ks * 32);
                bf[np * 2][0] = r0; bf[np * 2][1] = r1;
                bf[np * 2 + 1][0] = r2; bf[np * 2 + 1][1] = r3;
            }
            #pragma unroll
            for (int mi = 0; mi < 4; mi++)
                #pragma unroll
                for (int ni = 0; ni < 4; ni++)
                    mma16816(acc[mi][ni], af[mi], bf[ni]);
        }
        __syncthreads();
    }

    // prefetch W1 pair 0 (panels 0,1 @ kc 0) -> slot 0
    #pragma unroll
    for (int pl = 0; pl < 2; pl++) {
        const __nv_bfloat16* Wg = w1 + (size_t)(pl * 128) * 256;
        #pragma unroll
        for (int it = 0; it < 4; it++) {
            int row = crow + it * 32;
            cp_async16(sW + pl * STG + row * ROWB + cch * 16,
                       Wg + (size_t)row * 256 + cch * 8);
        }
    }
    CP_COMMIT();

    // ---- epilogue GEMM1: x = embed + acc*mk -> out ; stats ----
    int qrow = lane >> 2, qcol = (lane & 3) * 2;
    #pragma unroll
    for (int mi = 0; mi < 4; mi++) {
        #pragma unroll
        for (int half = 0; half < 2; half++) {
            int rloc = mi * 16 + qrow + half * 8;
            size_t row = (size_t)m0 + rloc;
            float mk = (float)rmask[row];
            float s1 = 0.f, s2 = 0.f;
            #pragma unroll
            for (int ni = 0; ni < 4; ni++) {
                int c = wn * 32 + ni * 8 + qcol;
                float2 e = *(const float2*)(embed + row * 256 + c);
                float x0 = e.x + acc[mi][ni][half * 2 + 0] * mk;
                float x1 = e.y + acc[mi][ni][half * 2 + 1] * mk;
                acc[mi][ni][half * 2 + 0] = x0;
                acc[mi][ni][half * 2 + 1] = x1;
                *(float2*)(out + row * 256 + c) = make_float2(x0, x1);
                s1 += x0 + x1;
                s2 += x0 * x0 + x1 * x1;
            }
            s1 += __shfl_xor_sync(0xffffffffu, s1, 1);
            s1 += __shfl_xor_sync(0xffffffffu, s1, 2);
            s2 += __shfl_xor_sync(0xffffffffu, s2, 1);
            s2 += __shfl_xor_sync(0xffffffffu, s2, 2);
            if ((lane & 3) == 0) {
                sred[rloc * 8 + wn] = s1;
                sred[512 + rloc * 8 + wn] = s2;
            }
        }
    }
    __syncthreads();
    if (tid < 64) {
        float a1 = 0.f, a2 = 0.f;
        #pragma unroll
        for (int w = 0; w < 8; w++) {
            a1 += sred[tid * 8 + w];
            a2 += sred[512 + tid * 8 + w];
        }
        float mu = a1 * (1.f / 256.f);
        float var = a2 * (1.f / 256.f) - mu * mu;
        smu[tid] = mu;
        srs[tid] = rsqrtf(var + 1e-5f);
    }
    __syncthreads();
    // ---- LN -> hln in SMEM @0 ----
    #pragma unroll
    for (int mi = 0; mi < 4; mi++) {
        #pragma unroll
        for (int half = 0; half < 2; half++) {
            int rloc = mi * 16 + qrow + half * 8;
            float mu = smu[rloc], rs = srs[rloc];
            #pragma unroll
            for (int ni = 0; ni < 4; ni++) {
                int c = wn * 32 + ni * 8 + qcol;
                float h0 = (acc[mi][ni][half * 2 + 0] - mu) * rs * gam[c] + bet[c];
                float h1v = (acc[mi][ni][half * 2 + 1] - mu) * rs * gam[c + 1] + bet[c + 1];
                *(__nv_bfloat162*)(dsm + rloc * ROWH + c * 2) =
                    __floats2bfloat162_rn(h0, h1v);
            }
        }
    }

    // ---- GEMM2: h1 = relu(hln @ W1^T + b1); (panel-pair, kc) iterations ----
    float acc2[2][4][2][4];
    #pragma unroll
    for (int pl = 0; pl < 2; pl++)
        #pragma unroll
        for (int mi = 0; mi < 4; mi++)
            #pragma unroll
            for (int nf = 0; nf < 2; nf++)
                #pragma unroll
                for (int u = 0; u < 4; u++) acc2[pl][mi][nf][u] = 0.f;

    uint32_t a2_off = (uint32_t)((lrow + (grp & 1) * 8) * ROWH + (grp >> 1) * 16);

    #pragma unroll 1
    for (int g2 = 0; g2 < 8; g2++) {
        CP_WAIT(0);
        __syncthreads();
        if (g2 + 1 < 8) {
            int pp1 = (g2 + 1) >> 2, kc1 = (g2 + 1) & 3;
            uint32_t dst = sW + (uint32_t)((g2 + 1) & 1) * (2 * STG);
            #pragma unroll
            for (int pl = 0; pl < 2; pl++) {
                const __nv_bfloat16* Wg =
                    w1 + (size_t)((2 * pp1 + pl) * 128) * 256 + kc1 * 64;
                #pragma unroll
                for (int it = 0; it < 4; it++) {
                    int row = crow + it * 32;
                    cp_async16(dst + pl * STG + row * ROWB + cch * 16,
                               Wg + (size_t)row * 256 + cch * 8);
                }
            }
            CP_COMMIT();
        }

        int kc = g2 & 3;
        uint32_t slot = sW + (uint32_t)(g2 & 1) * (2 * STG);
        #pragma unroll
        for (int ks = 0; ks < 4; ks++) {
            uint32_t af[4][4];
            #pragma unroll
            for (int mi = 0; mi < 4; mi++)
                ldsm_x4(af[mi][0], af[mi][1], af[mi][2], af[mi][3],
                        sH + mi * 16 * ROWH + a2_off + kc * 128 + ks * 32);
            #pragma unroll
            for (int pl = 0; pl < 2; pl++) {
                uint32_t bk[4];
                ldsm_x4(bk[0], bk[1], bk[2], bk[3],
                        slot + pl * STG + (wn * 16) * ROWB + b_off + ks * 32);
                #pragma unroll
                for (int mi = 0; mi < 4; mi++) {
                    mma16816(acc2[pl][mi][0], af[mi], bk);
                    mma16816(acc2[pl][mi][1], af[mi], bk + 2);
                }
            }
        }

        if (kc == 3) {
            int pp = g2 >> 2;
            #pragma unroll
            for (int pl = 0; pl < 2; pl++) {
                int p = 2 * pp + pl;
                #pragma unroll
                for (int mi = 0; mi < 4; mi++)
                    #pragma unroll
                    for (int half = 0; half < 2; half++) {
                        size_t row = (size_t)m0 + mi * 16 + qrow + half * 8;
                        #pragma unroll
                        for (int nf = 0; nf < 2; nf++) {
                            int c = p * 128 + wn * 16 + nf * 8 + qcol;
                            float r0 = fmaxf(acc2[pl][mi][nf][half * 2 + 0] + b1[c], 0.f);
                            float r1 = fmaxf(acc2[pl][mi][nf][half * 2 + 1] + b1[c + 1], 0.f);
                            *(__nv_bfloat162*)(h1 + row * 512 + c) =
                                __floats2bfloat162_rn(r0, r1);
                            acc2[pl][mi][nf][half * 2 + 0] = 0.f;
                            acc2[pl][mi][nf][half * 2 + 1] = 0.f;
                        }
                    }
            }
        }
    }
}

// ============ combined weight-transpose + both input LayerNorms =============
__device__ __forceinline__ void wt_seg(const float* W, __nv_bfloat16* Wt,
                                       int idx, int N, int K) {
    int k = idx / N, n = idx % N;
    Wt[(size_t)n * K + k] = __float2bfloat16(W[idx]);
}
__device__ __forceinline__ void ln_token(
    const float* __restrict__ xr, const float* __restrict__ gam,
    const float* __restrict__ bet, __nv_bfloat16* __restrict__ yr, int lane)
{
    const float2* x2 = (const float2*)xr;
    float2 v[4];
    #pragma unroll
    for (int u = 0; u < 4; u++) v[u] = x2[lane + 32 * u];
    float s = 0.f;
    #pragma unroll
    for (int u = 0; u < 4; u++) s += v[u].x + v[u].y;
    #pragma unroll
    for (int o = 16; o; o >>= 1) s += __shfl_xor_sync(0xffffffffu, s, o);
    float mu = s * (1.f / 256.f);
    float ss = 0.f;
    float2 d[4];
    #pragma unroll
    for (int u = 0; u < 4; u++) {
        d[u].x = v[u].x - mu; d[u].y = v[u].y - mu;
        ss += d[u].x * d[u].x + d[u].y * d[u].y;
    }
    #pragma unroll
    for (int o = 16; o; o >>= 1) ss += __shfl_xor_sync(0xffffffffu, ss, o);
    float r = rsqrtf(ss * (1.f / 256.f) + 1e-5f);
    const float2* g2 = (const float2*)gam;
    const float2* b2 = (const float2*)bet;
    __nv_bfloat162* y2 = (__nv_bfloat162*)yr;
    #pragma unroll
    for (int u = 0; u < 4; u++) {
        int c2 = lane + 32 * u;
        float2 g = g2[c2], b = b2[c2];
        y2[c2] = __floats2bfloat162_rn(d[u].x * r * g.x + b.x,
                                       d[u].y * r * g.y + b.y);
    }
}

#define LN_BLOCKS ((MQ + MK) / 8)   /* 15360 */
__global__ __launch_bounds__(256) void prep_kernel(
    const float* __restrict__ embed, const float* __restrict__ memory,
    const float* __restrict__ sq, const float* __restrict__ bq,
    const float* __restrict__ skv, const float* __restrict__ bkv,
    __nv_bfloat16* __restrict__ qe, __nv_bfloat16* __restrict__ km,
    const float* __restrict__ Wq, const float* __restrict__ Wgate,
    const float* __restrict__ Wkv, const float* __restrict__ Wout,
    const float* __restrict__ W1, const float* __restrict__ W2,
    __nv_bfloat16* __restrict__ wqg, __nv_bfloat16* __restrict__ wkv,
    __nv_bfloat16* __restrict__ wo, __nv_bfloat16* __restrict__ w1,
    __nv_bfloat16* __restrict__ w2)
{
    if (blockIdx.x < LN_BLOCKS) {
        int gw   = (blockIdx.x * 256 + threadIdx.x) >> 5;
        int lane = threadIdx.x & 31;
        if (gw < MQ) {
            ln_token(embed + (size_t)gw * 256, sq, bq, qe + (size_t)gw * 256, lane);
        } else {
            size_t t = gw - MQ;
            ln_token(memory + t * 256, skv, bkv, km + t * 256, lane);
        }
    } else {
        int idx = (blockIdx.x - LN_BLOCKS) * 256 + threadIdx.x;
        if (idx < 65536)                { wt_seg(Wq,    wqg,         idx,          256, 256); return; }
        if (idx < 2*65536)              { wt_seg(Wgate, wqg + 65536, idx - 65536,  256, 256); return; }
        if (idx < 2*65536 + 131072)     { wt_seg(Wkv,   wkv,         idx - 131072, 512, 256); return; }
        if (idx < 3*65536 + 131072)     { wt_seg(Wout,  wo,          idx - 262144, 256, 256); return; }
        if (idx < 3*65536 + 2*131072)   { wt_seg(W1,    w1,          idx - 327680, 512, 256); return; }
        if (idx < 3*65536 + 3*131072)   { wt_seg(W2,    w2,          idx - 458752, 256, 512); return; }
    }
}

// =============== MMA attention v4 (head-axis softmax) — R15 best ============
#define ROWQ 528
#define KVBUF (2 * 32 * ROWQ)
#define PB_PLANE 2560
#define SMEM_ATT (32 * ROWQ + KVBUF + 8 * PB_PLANE)   /* 71168 */
__global__ __launch_bounds__(256, 3) void attention_mma_kernel(
    const __nv_bfloat16* __restrict__ qg,
    const __nv_bfloat16* __restrict__ kv,
    const int*  __restrict__ rmask,
    const int*  __restrict__ mmask,
    __nv_bfloat16* __restrict__ out)
{
    extern __shared__ char sm8[];
    const uint32_t sQ = smem_u32(sm8);
    const uint32_t sK = sQ + 32 * ROWQ;
    const uint32_t sV = sK + 32 * ROWQ;
    const uint32_t sP = sQ + 32 * ROWQ + KVBUF;
    char* Pb = sm8 + 32 * ROWQ + KVBUF;
    __shared__ float rm[32];
    __shared__ float mb6[64];

    int n = blockIdx.x, i0 = blockIdx.y * 32;
    int tid = threadIdx.x, lane = tid & 31, h = tid >> 5;
    int lrow = lane & 7, grp = lane >> 3;

    if (tid < 64) mb6[tid] = (float)mmask[tid * N_DIM + n] * 1e6f;
    if (tid < 32) rm[tid] = (float)rmask[(i0 + tid) * N_DIM + n];

    #pragma unroll
    for (int it = 0; it < 4; it++) {
        int q = tid + it * 256;
        int row = q >> 5, c = q & 31;
        cp_async16(sQ + row * ROWQ + c * 16,
                   qg + ((size_t)(i0 + row) * N_DIM + n) * 512 + c * 8);
    }
    #pragma unroll
    for (int it = 0; it < 8; it++) {
        int idx = tid + it * 256;
        int row = idx >> 6, c = idx & 63;
        uint32_t dst = (c < 32) ? (sK + row * ROWQ + c * 16)
                                : (sV + row * ROWQ + (c - 32) * 16);
        cp_async16(dst, kv + ((size_t)row * N_DIM + n) * 512 + c * 8);
    }
    CP_COMMIT();

    float acc_o[2][4][4];
    #pragma unroll
    for (int mi = 0; mi < 2; mi++)
        #pragma unroll
        for (int nb = 0; nb < 4; nb++)
            #pragma unroll
            for (int e = 0; e < 4; e++) acc_o[mi][nb][e] = 0.f;

    CP_WAIT(0);
    __syncthreads();

    #pragma unroll 1
    for (int ph = 0; ph < 2; ph++) {
        float acc_s[2][4][4];
        #pragma unroll
        for (int mi = 0; mi < 2; mi++)
            #pragma unroll
            for (int jb = 0; jb < 4; jb++)
                #pragma unroll
                for (int e = 0; e < 4; e++) acc_s[mi][jb][e] = 0.f;

        #pragma unroll
        for (int ks = 0; ks < 2; ks++) {
            uint32_t aq[2][4];
            #pragma unroll
            for (int mi = 0; mi < 2; mi++)
                ldsm_x4(aq[mi][0], aq[mi][1], aq[mi][2], aq[mi][3],
                        sQ + (mi * 16 + lrow + (grp & 1) * 8) * ROWQ
                           + h * 64 + ks * 32 + (grp >> 1) * 16);
            #pragma unroll
            for (int jbp = 0; jbp < 2; jbp++) {
                uint32_t bk[4];
                ldsm_x4(bk[0], bk[1], bk[2], bk[3],
                        sK + (jbp * 16 + lrow + (grp >> 1) * 8) * ROWQ
                           + h * 64 + ks * 32 + (grp & 1) * 16);
                #pragma unroll
                for (int mi = 0; mi < 2; mi++) {
                    mma16816(acc_s[mi][jbp * 2],     aq[mi], bk);
                    mma16816(acc_s[mi][jbp * 2 + 1], aq[mi], bk + 2);
                }
            }
        }

        #pragma unroll
        for (int mi = 0; mi < 2; mi++)
            #pragma unroll
            for (int jb = 0; jb < 4; jb++)
                #pragma unroll
                for (int half = 0; half < 2; half++) {
                    int i = mi * 16 + (lane >> 2) + half * 8;
                    int j = jb * 8 + (lane & 3) * 2;
                    float b0 = fmaf(rm[i], mb6[ph * 32 + j],     -1e6f);
                    float b1 = fmaf(rm[i], mb6[ph * 32 + j + 1], -1e6f);
                    float p0 = __expf((acc_s[mi][jb][half * 2 + 0] + b0) - b0);
                    float p1 = __expf((acc_s[mi][jb][half * 2 + 1] + b1) - b1);
                    *(__nv_bfloat162*)(Pb + h * PB_PLANE + i * 80 + j * 2) =
                        __floats2bfloat162_rn(p0, p1);
                }
        __syncthreads();   // exp visible; all warps done reading K

        if (ph == 0) {
            #pragma unroll
            for (int it = 0; it < 4; it++) {
                int idx = tid + it * 256;
                int row = idx >> 5, c = idx & 31;
                cp_async16(sK + row * ROWQ + c * 16,
                           kv + ((size_t)(32 + row) * N_DIM + n) * 512 + c * 8);
            }
            CP_COMMIT();
        }

        #pragma unroll
        for (int t = 0; t < 2; t++) {
            int idx = tid + t * 256;
            int i = idx >> 4, jp = idx & 15;
            char* base = Pb + i * 80 + jp * 4;
            float2 pv[8];
            float s0 = 0.f, s1 = 0.f;
            #pragma unroll
            for (int hh = 0; hh < 8; hh++) {
                pv[hh] = __bfloat1622float2(
                    *(const __nv_bfloat162*)(base + hh * PB_PLANE));
                s0 += pv[hh].x;
                s1 += pv[hh].y;
            }
            float inv0 = __fdividef(1.f, s0);
            float inv1 = __fdividef(1.f, s1);
            #pragma unroll
            for (int hh = 0; hh < 8; hh++)
                *(__nv_bfloat162*)(base + hh * PB_PLANE) =
                    __floats2bfloat162_rn(pv[hh].x * inv0, pv[hh].y * inv1);
        }
        if (ph == 1) CP_WAIT(0);   // V1 landed (had QK+exp+softmax to hide)
        __syncthreads();

        #pragma unroll
        for (int ks = 0; ks < 2; ks++) {
            uint32_t ap[2][4];
            #pragma unroll
            for (int mi = 0; mi < 2; mi++)
                ldsm_x4(ap[mi][0], ap[mi][1], ap[mi][2], ap[mi][3],
                        sP + h * PB_PLANE + (mi * 16 + lrow + (grp & 1) * 8) * 80
                           + ks * 32 + (grp >> 1) * 16);
            #pragma unroll
            for (int cb = 0; cb < 2; cb++) {
                uint32_t bv[4];
                ldsm_x4_trans(bv[0], bv[1], bv[2], bv[3],
                        sV + (ks * 16 + lrow + (grp & 1) * 8) * ROWQ
                           + h * 64 + cb * 32 + (grp >> 1) * 16);
                #pragma unroll
                for (int mi = 0; mi < 2; mi++) {
                    mma16816(acc_o[mi][cb * 2],     ap[mi], bv);
                    mma16816(acc_o[mi][cb * 2 + 1], ap[mi], bv + 2);
                }
            }
        }
        __syncthreads();

        if (ph == 0) {
            #pragma unroll
            for (int it = 0; it < 4; it++) {
                int idx = tid + it * 256;
                int row = idx >> 5, c = idx & 31;
                cp_async16(sV + row * ROWQ + c * 16,
                           kv + ((size_t)(32 + row) * N_DIM + n) * 512
                              + 256 + c * 8);
            }
            CP_COMMIT();
            CP_WAIT(1);            // K1 landed; V1 still in flight
            __syncthreads();
        }
    }

    #pragma unroll
    for (int mi = 0; mi < 2; mi++)
        #pragma unroll
        for (int half = 0; half < 2; half++) {
            size_t R = (size_t)(i0 + mi * 16 + (lane >> 2) + half * 8);
            const __nv_bfloat16* gp = qg + (R * N_DIM + n) * 512 + 256 + h * 32;
            __nv_bfloat16* op = out + (R * N_DIM + n) * 256 + h * 32;
            #pragma unroll
            for (int nb = 0; nb < 4; nb++) {
                int ch = nb * 8 + (lane & 3) * 2;
                __nv_bfloat162 g = *(const __nv_bfloat162*)(gp + ch);
                float gx = __bfloat162float(g.x), gy = __bfloat162float(g.y);
                float r0 = acc_o[mi][nb][half * 2 + 0]
                           * __fdividef(1.f, 1.f + __expf(-gx));
                float r1 = acc_o[mi][nb][half * 2 + 1]
                           * __fdividef(1.f, 1.f + __expf(-gy));
                *(__nv_bfloat162*)(op + ch) = __floats2bfloat162_rn(r0, r1);
            }
        }
}

// ---------------- launch -----------------------------------------------------
extern "C" void kernel_launch(void* const* d_in, const int* in_sizes, int n_in,
                              void* d_out, int out_size)
{
    const float* embed   = (const float*)d_in[0];
    const float* memory  = (const float*)d_in[1];
    const int*   rmask   = (const int*)  d_in[2];
    const int*   mmask   = (const int*)  d_in[3];
    const float* ln_q_s  = (const float*)d_in[4];
    const float* ln_q_b  = (const float*)d_in[5];
    const float* ln_kv_s = (const float*)d_in[6];
    const float* ln_kv_b = (const float*)d_in[7];
    const float* Wq      = (const float*)d_in[8];
    const float* Wkv     = (const float*)d_in[9];
    const float* Wgate   = (const float*)d_in[10];
    const float* Wout    = (const float*)d_in[11];
    const float* ln_f_s  = (const float*)d_in[12];
    const float* ln_f_b  = (const float*)d_in[13];
    const float* W1      = (const float*)d_in[14];
    const float* b1      = (const float*)d_in[15];
    const float* W2      = (const float*)d_in[16];
    const float* b2      = (const float*)d_in[17];
    float* out = (float*)d_out;

    __nv_bfloat16 *qe, *km, *qgb, *kvb, *ab, *h1;
    __nv_bfloat16 *wqg, *wkv, *wo, *w1, *w2;
    cudaGetSymbolAddress((void**)&qe,  g_qe);
    cudaGetSymbolAddress((void**)&km,  g_km);
    cudaGetSymbolAddress((void**)&qgb, g_qg);
    cudaGetSymbolAddress((void**)&kvb, g_kv);
    cudaGetSymbolAddress((void**)&ab,  g_ab);
    cudaGetSymbolAddress((void**)&h1,  g_h1);
    cudaGetSymbolAddress((void**)&wqg, g_Wqg);
    cudaGetSymbolAddress((void**)&wkv, g_Wkv);
    cudaGetSymbolAddress((void**)&wo,  g_Wo);
    cudaGetSymbolAddress((void**)&w1,  g_W1);
    cudaGetSymbolAddress((void**)&w2,  g_W2);

    const int SMEM_GEMM = 4 * STG;
    cudaFuncSetAttribute(qgkv_gemm,            cudaFuncAttributeMaxDynamicSharedMemorySize, SMEM_BRES);
    cudaFuncSetAttribute(mma_gemm<3, false>,   cudaFuncAttributeMaxDynamicSharedMemorySize, SMEM_GEMM);
    cudaFuncSetAttribute(gemm_ln_ffn1_kernel,  cudaFuncAttributeMaxDynamicSharedMemorySize, SMEM_GLN);
    cudaFuncSetAttribute(attention_mma_kernel, cudaFuncAttributeMaxDynamicSharedMemorySize, SMEM_ATT);

    // idx 0: combined LN(inputs) + all weight transposes
    prep_kernel<<<LN_BLOCKS + (589824 + 255) / 256, 256>>>(
        embed, memory, ln_q_s, ln_q_b, ln_kv_s, ln_kv_b, qe, km,
        Wq, Wgate, Wkv, Wout, W1, W2, wqg, wkv, wo, w1, w2);
    // idx 1: q|gate (z=0) and kv (z=1) projections
    qgkv_gemm<<<dim3(4, 192, 2), 256, SMEM_BRES>>>(qe, wqg, qgb, km, wkv, kvb);
    // idx 2: MMA attention + sigmoid gating (3 CTAs/SM, R15 config)
    attention_mma_kernel<<<dim3(N_DIM, 8), 256, SMEM_ATT>>>(qgb, kvb,
                                                            rmask, mmask, ab);
    // idx 3: fused x=embed+(ab@Wo)*rmask -> out ; LN ; h1 (PROFILED)
    gemm_ln_ffn1_kernel<<<MQ / 64, 256, SMEM_GLN>>>(ab, wo, embed, rmask,
                                                    ln_f_s, ln_f_b, w1, b1,
                                                    out, h1);
    // idx 4: FFN2
    mma_gemm<3, false><<<dim3(2, MQ / 128), 256, SMEM_GEMM>>>(
        h1, w2, out, 256, 512, b2, out, rmask);
}